// round 2
// baseline (speedup 1.0000x reference)
#include <cuda_runtime.h>
#include <cuda_bf16.h>
#include <cstdint>

// Problem constants
#define B_  4
#define T_  2048
#define C_  1024
#define NH  16
#define HD  64
#define M_  (B_*T_)          // 8192 rows

// Scratch (device globals: allocation-free per harness rules)
__device__ float g_qkv[(size_t)M_ * 3 * C_];   // ~100 MB
__device__ float g_y  [(size_t)M_ * C_];       // ~33 MB

// ---------------------------------------------------------------- helpers
__device__ __forceinline__ uint32_t smem_u32(const void* p){
    uint32_t a;
    asm("{ .reg .u64 t; cvta.to.shared.u64 t, %1; cvt.u32.u64 %0, t; }"
        : "=r"(a) : "l"(p));
    return a;
}
__device__ __forceinline__ void cp16(void* sm, const void* gm){
    asm volatile("cp.async.cg.shared.global [%0], [%1], 16;"
                 :: "r"(smem_u32(sm)), "l"(gm));
}
__device__ __forceinline__ void cp_commit(){ asm volatile("cp.async.commit_group;"); }
template<int N> __device__ __forceinline__ void cp_wait(){
    asm volatile("cp.async.wait_group %0;" :: "n"(N));
}
__device__ __forceinline__ uint32_t f2tf(float f){
    uint32_t r; asm("cvt.rna.tf32.f32 %0, %1;" : "=r"(r) : "f"(f)); return r;
}
// m16n8k8 tf32 MMA, fp32 accumulate (in place)
__device__ __forceinline__ void mma8(float* c,
    uint32_t a0,uint32_t a1,uint32_t a2,uint32_t a3,uint32_t b0,uint32_t b1){
    asm volatile("mma.sync.aligned.m16n8k8.row.col.f32.tf32.tf32.f32 "
        "{%0,%1,%2,%3}, {%4,%5,%6,%7}, {%8,%9}, {%0,%1,%2,%3};"
        : "+f"(c[0]),"+f"(c[1]),"+f"(c[2]),"+f"(c[3])
        : "r"(a0),"r"(a1),"r"(a2),"r"(a3),"r"(b0),"r"(b1));
}

// ---------------------------------------------------------------- GEMM
// C[M,N] = A[M,K] @ B[K,N], all row-major, fp32 in/out, tf32 MMA.
// Block tile 128x128, K-block 16, 2-stage cp.async pipeline, 256 threads.
#define BK   16
#define ASTR 20      // 16 + 4 pad (keeps 16B alignment: 20*4=80 B rows)
#define BSTR 132     // 128 + 4 pad (132*4=528 B rows)
#define STG  (128*ASTR + BK*BSTR)   // 2560 + 2112 = 4672 floats per stage

template<int N, int K>
__device__ __forceinline__ void gemm_body(const float* __restrict__ A,
                                          const float* __restrict__ Bm,
                                          float* __restrict__ C)
{
    __shared__ float sm[2*STG];     // 37376 B, static (<48K: no attr needed)
    const int tid  = threadIdx.x;
    const long bm  = (long)blockIdx.y * 128;
    const long bn  = (long)blockIdx.x * 128;
    const int warp = tid >> 5, lane = tid & 31;
    const int wm   = (warp >> 2) << 6;   // 0 / 64
    const int wn   = (warp & 3) << 5;    // 0 / 32 / 64 / 96
    const int g    = lane >> 2, tg = lane & 3;

    float acc[4][4][4];
    #pragma unroll
    for(int i=0;i<4;i++)
        #pragma unroll
        for(int j=0;j<4;j++)
            #pragma unroll
            for(int k=0;k<4;k++) acc[i][j][k]=0.f;

    const int arow = tid >> 2;           // 0..63 (two passes -> 128 rows)
    const int acol = (tid & 3) << 2;     // 0,4,8,12
    const int brow = tid >> 5;           // 0..7  (two passes -> 16 rows)
    const int bcol = (tid & 31) << 2;    // 0..124

    const int NK = K / BK;

    // stage 0 prefetch
    {
        float* As = sm; float* Bs = sm + 128*ASTR;
        cp16(&As[ arow     *ASTR + acol], &A[(bm+arow   )*(long)K + acol]);
        cp16(&As[(arow+64) *ASTR + acol], &A[(bm+arow+64)*(long)K + acol]);
        cp16(&Bs[ brow     *BSTR + bcol], &Bm[(long)(brow  )*N + bn + bcol]);
        cp16(&Bs[(brow+8)  *BSTR + bcol], &Bm[(long)(brow+8)*N + bn + bcol]);
        cp_commit();
    }

    for(int kb=0; kb<NK; ++kb){
        if(kb+1 < NK){
            const int kn = (kb+1)*BK;
            float* As = sm + ((kb+1)&1)*STG; float* Bs = As + 128*ASTR;
            cp16(&As[ arow     *ASTR + acol], &A[(bm+arow   )*(long)K + kn + acol]);
            cp16(&As[(arow+64) *ASTR + acol], &A[(bm+arow+64)*(long)K + kn + acol]);
            cp16(&Bs[ brow     *BSTR + bcol], &Bm[(long)(kn+brow  )*N + bn + bcol]);
            cp16(&Bs[(brow+8)  *BSTR + bcol], &Bm[(long)(kn+brow+8)*N + bn + bcol]);
            cp_commit();
            cp_wait<1>();
        } else {
            cp_wait<0>();
        }
        __syncthreads();

        const float* As = sm + (kb&1)*STG;
        const float* Bs = As + 128*ASTR;
        #pragma unroll
        for(int ks=0; ks<BK/8; ++ks){
            uint32_t a[4][4], bq[4][2];
            const int c0 = ks*8 + tg;
            #pragma unroll
            for(int mt=0;mt<4;mt++){
                const int r = wm + mt*16 + g;
                a[mt][0]=f2tf(As[ r   *ASTR + c0  ]);
                a[mt][1]=f2tf(As[(r+8)*ASTR + c0  ]);
                a[mt][2]=f2tf(As[ r   *ASTR + c0+4]);
                a[mt][3]=f2tf(As[(r+8)*ASTR + c0+4]);
            }
            #pragma unroll
            for(int nt=0;nt<4;nt++){
                const int n = wn + nt*8 + g;
                bq[nt][0]=f2tf(Bs[(ks*8+tg  )*BSTR + n]);
                bq[nt][1]=f2tf(Bs[(ks*8+tg+4)*BSTR + n]);
            }
            #pragma unroll
            for(int mt=0;mt<4;mt++)
                #pragma unroll
                for(int nt=0;nt<4;nt++)
                    mma8(acc[mt][nt], a[mt][0],a[mt][1],a[mt][2],a[mt][3],
                         bq[nt][0],bq[nt][1]);
        }
        __syncthreads();
    }

    // epilogue
    #pragma unroll
    for(int mt=0;mt<4;mt++){
        const long r = bm + wm + mt*16 + g;
        #pragma unroll
        for(int nt=0;nt<4;nt++){
            const long col = bn + wn + nt*8 + 2*tg;
            *(float2*)&C[ r   *N + col] = make_float2(acc[mt][nt][0], acc[mt][nt][1]);
            *(float2*)&C[(r+8)*N + col] = make_float2(acc[mt][nt][2], acc[mt][nt][3]);
        }
    }
}

__global__ void __launch_bounds__(256) k_qkv(const float* __restrict__ x,
                                             const float* __restrict__ w){
    gemm_body<3*C_, C_>(x, w, g_qkv);
}
__global__ void __launch_bounds__(256) k_proj(const float* __restrict__ w,
                                              float* __restrict__ out){
    gemm_body<C_, C_>(g_y, w, out);
}

// ---------------------------------------------------------------- attention
// P fragment relayout: MMA C-layout (16x8) -> A-layout (16x8) via shuffles.
__device__ __forceinline__ void frag_c2a(float p0,float p1,float p2,float p3,
    uint32_t&a0,uint32_t&a1,uint32_t&a2,uint32_t&a3, int lane){
    const int tg   = lane & 3;
    const int base = lane & 28;
    const int src  = base | (tg >> 1);
    float v0=__shfl_sync(0xffffffffu,p0,src);
    float v1=__shfl_sync(0xffffffffu,p1,src);
    float v2=__shfl_sync(0xffffffffu,p2,src);
    float v3=__shfl_sync(0xffffffffu,p3,src);
    float w0=__shfl_sync(0xffffffffu,p0,src+2);
    float w1=__shfl_sync(0xffffffffu,p1,src+2);
    float w2=__shfl_sync(0xffffffffu,p2,src+2);
    float w3=__shfl_sync(0xffffffffu,p3,src+2);
    const bool hi = tg & 1;
    a0 = f2tf(hi?v1:v0); a1 = f2tf(hi?v3:v2);
    a2 = f2tf(hi?w1:w0); a3 = f2tf(hi?w3:w2);
}

// One block per (64-row Q tile, batch*head). 4 warps, each owns 16 Q rows.
__global__ void __launch_bounds__(128) k_attn()
{
    __shared__ float Ks[64*68];   // 17408 B
    __shared__ float Vs[64*68];   // 17408 B  (total 34816 B static)

    const int qt  = blockIdx.x;          // 0..31  (q tile)
    const int bh  = blockIdx.y;          // 0..63
    const int b   = bh >> 4, h = bh & 15;
    const int tid = threadIdx.x;
    const int warp= tid >> 5, lane = tid & 31;
    const int g   = lane >> 2, tg = lane & 3;
    const int qr  = warp << 4;           // warp's first q row inside tile

    const long RS = 3*C_;                // qkv row stride (3072)
    const float* base = g_qkv + (long)b*T_*RS;
    const float* Qg = base + (long)(qt*64)*RS + h*HD;
    const float* Kg = base + C_   + h*HD;
    const float* Vg = base + 2*C_ + h*HD;

    // ---- stage Q (scaled by 1/sqrt(64)=0.125) into Ks, build A-fragments
    #pragma unroll
    for(int i=0;i<8;i++){
        int idx = tid + i*128;               // 0..1023
        int r = idx >> 4, c = (idx & 15) << 2;
        float4 v = *(const float4*)&Qg[(long)r*RS + c];
        Ks[r*68+c  ] = v.x*0.125f;
        Ks[r*68+c+1] = v.y*0.125f;
        Ks[r*68+c+2] = v.z*0.125f;
        Ks[r*68+c+3] = v.w*0.125f;
    }
    __syncthreads();
    uint32_t qf[8][4];
    #pragma unroll
    for(int kt=0;kt<8;kt++){
        const int c = kt*8 + tg;
        qf[kt][0]=f2tf(Ks[(qr+g  )*68 + c  ]);
        qf[kt][1]=f2tf(Ks[(qr+g+8)*68 + c  ]);
        qf[kt][2]=f2tf(Ks[(qr+g  )*68 + c+4]);
        qf[kt][3]=f2tf(Ks[(qr+g+8)*68 + c+4]);
    }
    __syncthreads();

    float o[8][4];
    #pragma unroll
    for(int dt=0;dt<8;dt++){ o[dt][0]=0;o[dt][1]=0;o[dt][2]=0;o[dt][3]=0; }
    float m0=-1e30f, m1=-1e30f, l0=0.f, l1=0.f;

    for(int j=0;j<=qt;j++){
        // ---- load K tile (group 1) and V tile (group 0) separately so the
        //      S-MMA can start as soon as K lands, overlapping V's tail.
        const float* Kj = Kg + (long)(j*64)*RS;
        const float* Vj = Vg + (long)(j*64)*RS;
        #pragma unroll
        for(int i=0;i<8;i++){
            int idx = tid + i*128;
            int r = idx >> 4, c = (idx & 15) << 2;
            cp16(&Ks[r*68+c], &Kj[(long)r*RS + c]);
        }
        cp_commit();
        #pragma unroll
        for(int i=0;i<8;i++){
            int idx = tid + i*128;
            int r = idx >> 4, c = (idx & 15) << 2;
            cp16(&Vs[r*68+c], &Vj[(long)r*RS + c]);
        }
        cp_commit();
        cp_wait<1>();          // K tile complete (V may still be in flight)
        __syncthreads();

        // ---- S = (Q*scale) @ K^T   (16 q-rows x 64 keys per warp)
        float s[8][4];
        #pragma unroll
        for(int nt=0;nt<8;nt++){ s[nt][0]=0;s[nt][1]=0;s[nt][2]=0;s[nt][3]=0; }
        #pragma unroll
        for(int kt=0;kt<8;kt++){
            #pragma unroll
            for(int nt=0;nt<8;nt++){
                const int n = nt*8+g, kr = kt*8+tg;
                uint32_t b0=f2tf(Ks[n*68+kr  ]);
                uint32_t b1=f2tf(Ks[n*68+kr+4]);
                mma8(s[nt], qf[kt][0],qf[kt][1],qf[kt][2],qf[kt][3], b0,b1);
            }
        }

        // ---- causal mask on the diagonal tile
        if(j==qt){
            const int r0 = qr+g, r1 = r0+8;
            #pragma unroll
            for(int nt=0;nt<8;nt++){
                const int c0 = nt*8 + 2*tg;
                if(c0   > r0) s[nt][0] = -1e30f;
                if(c0+1 > r0) s[nt][1] = -1e30f;
                if(c0   > r1) s[nt][2] = -1e30f;
                if(c0+1 > r1) s[nt][3] = -1e30f;
            }
        }

        // ---- online softmax (rows r0 = qr+g, r1 = qr+g+8)
        float mx0=-1e30f, mx1=-1e30f;
        #pragma unroll
        for(int nt=0;nt<8;nt++){
            mx0 = fmaxf(mx0, fmaxf(s[nt][0], s[nt][1]));
            mx1 = fmaxf(mx1, fmaxf(s[nt][2], s[nt][3]));
        }
        mx0 = fmaxf(mx0, __shfl_xor_sync(0xffffffffu, mx0, 1));
        mx0 = fmaxf(mx0, __shfl_xor_sync(0xffffffffu, mx0, 2));
        mx1 = fmaxf(mx1, __shfl_xor_sync(0xffffffffu, mx1, 1));
        mx1 = fmaxf(mx1, __shfl_xor_sync(0xffffffffu, mx1, 2));
        const float mn0 = fmaxf(m0, mx0), mn1 = fmaxf(m1, mx1);
        const float al0 = __expf(m0 - mn0), al1 = __expf(m1 - mn1);
        m0 = mn0; m1 = mn1;
        float su0 = 0.f, su1 = 0.f;
        #pragma unroll
        for(int nt=0;nt<8;nt++){
            s[nt][0]=__expf(s[nt][0]-mn0); s[nt][1]=__expf(s[nt][1]-mn0);
            s[nt][2]=__expf(s[nt][2]-mn1); s[nt][3]=__expf(s[nt][3]-mn1);
            su0 += s[nt][0]+s[nt][1];
            su1 += s[nt][2]+s[nt][3];
        }
        su0 += __shfl_xor_sync(0xffffffffu, su0, 1);
        su0 += __shfl_xor_sync(0xffffffffu, su0, 2);
        su1 += __shfl_xor_sync(0xffffffffu, su1, 1);
        su1 += __shfl_xor_sync(0xffffffffu, su1, 2);
        l0 = l0*al0 + su0; l1 = l1*al1 + su1;
        #pragma unroll
        for(int dt=0;dt<8;dt++){
            o[dt][0]*=al0; o[dt][1]*=al0; o[dt][2]*=al1; o[dt][3]*=al1;
        }

        // ---- O += P @ V  (shuffle-transpose P into A-layout, no smem)
        cp_wait<0>();          // V tile complete
        __syncthreads();
        #pragma unroll
        for(int kt=0;kt<8;kt++){
            uint32_t a0,a1,a2,a3;
            frag_c2a(s[kt][0],s[kt][1],s[kt][2],s[kt][3], a0,a1,a2,a3, lane);
            #pragma unroll
            for(int dt=0;dt<8;dt++){
                uint32_t b0=f2tf(Vs[(kt*8+tg  )*68 + dt*8+g]);
                uint32_t b1=f2tf(Vs[(kt*8+tg+4)*68 + dt*8+g]);
                mma8(o[dt], a0,a1,a2,a3, b0,b1);
            }
        }
        __syncthreads();   // Ks/Vs fully consumed before next tile load
    }

    // ---- epilogue: O / l -> g_y laid out [B*T, C] with head offset
    const float i0 = 1.f/l0, i1 = 1.f/l1;
    const long r0 = (long)(b*T_ + qt*64 + qr + g);
    #pragma unroll
    for(int dt=0;dt<8;dt++){
        const long col = h*HD + dt*8 + 2*tg;
        *(float2*)&g_y[ r0   *C_ + col] = make_float2(o[dt][0]*i0, o[dt][1]*i0);
        *(float2*)&g_y[(r0+8)*C_ + col] = make_float2(o[dt][2]*i1, o[dt][3]*i1);
    }
}

// ---------------------------------------------------------------- launch
extern "C" void kernel_launch(void* const* d_in, const int* in_sizes, int n_in,
                              void* d_out, int out_size)
{
    const float* x     = (const float*)d_in[0];   // (4,2048,1024)
    const float* wqkv  = (const float*)d_in[1];   // (1024,3072)
    const float* wproj = (const float*)d_in[2];   // (1024,1024)
    float* out = (float*)d_out;                   // (4,2048,1024)

    k_qkv <<<dim3(3*C_/128, M_/128), 256>>>(x, wqkv);
    k_attn<<<dim3(T_/64, B_*NH),     128>>>();
    k_proj<<<dim3(C_/128, M_/128),   256>>>(wproj, out);
}

// round 5
// speedup vs baseline: 1.0120x; 1.0120x over previous
#include <cuda_runtime.h>
#include <cuda_bf16.h>
#include <cstdint>

// Problem constants
#define B_  4
#define T_  2048
#define C_  1024
#define NH  16
#define HD  64
#define M_  (B_*T_)          // 8192 rows

// Scratch (device globals: allocation-free per harness rules)
__device__ float g_qkv [(size_t)M_ * 3 * C_];   // tf32-rounded QKV
__device__ float g_y   [(size_t)M_ * C_];       // tf32-rounded attn out
__device__ float g_x   [(size_t)M_ * C_];       // tf32-rounded x
__device__ float g_wqkv[(size_t)C_ * 3 * C_];   // tf32-rounded w_qkv [K,N]
__device__ float g_wprj[(size_t)C_ * C_];       // tf32-rounded w_proj [K,N]

// ---------------------------------------------------------------- helpers
__device__ __forceinline__ uint32_t smem_u32(const void* p){
    uint32_t a;
    asm("{ .reg .u64 t; cvta.to.shared.u64 t, %1; cvt.u32.u64 %0, t; }"
        : "=r"(a) : "l"(p));
    return a;
}
__device__ __forceinline__ void cp16(void* sm, const void* gm){
    asm volatile("cp.async.cg.shared.global [%0], [%1], 16;"
                 :: "r"(smem_u32(sm)), "l"(gm));
}
__device__ __forceinline__ void cp_commit(){ asm volatile("cp.async.commit_group;"); }
template<int N> __device__ __forceinline__ void cp_wait(){
    asm volatile("cp.async.wait_group %0;" :: "n"(N));
}
__device__ __forceinline__ uint32_t f2tf(float f){
    uint32_t r; asm("cvt.rna.tf32.f32 %0, %1;" : "=r"(r) : "f"(f)); return r;
}
__device__ __forceinline__ float rtf(float f){ return __uint_as_float(f2tf(f)); }

// m16n8k8 tf32 MMA, fp32 accumulate (in place)
__device__ __forceinline__ void mma8(float* c,
    uint32_t a0,uint32_t a1,uint32_t a2,uint32_t a3,uint32_t b0,uint32_t b1){
    asm volatile("mma.sync.aligned.m16n8k8.row.col.f32.tf32.tf32.f32 "
        "{%0,%1,%2,%3}, {%4,%5,%6,%7}, {%8,%9}, {%0,%1,%2,%3};"
        : "+f"(c[0]),"+f"(c[1]),"+f"(c[2]),"+f"(c[3])
        : "r"(a0),"r"(a1),"r"(a2),"r"(a3),"r"(b0),"r"(b1));
}

// ---------------------------------------------------------------- prep
__global__ void k_round(const float* __restrict__ in, float* __restrict__ out, int n){
    int i = blockIdx.x*blockDim.x + threadIdx.x;
    const int str = gridDim.x*blockDim.x;
    for(; i < n; i += str) out[i] = rtf(in[i]);
}

// ---------------------------------------------------------------- GEMM
// C[M,N] = A[M,K] @ B[K,N], row-major, inputs ALREADY tf32-rounded.
// Block tile 128x128, K-block 16, 2-stage cp.async, 256 threads (8 warps).
#define BK   16
#define ASTR 20
#define BSTR 132
#define STG  (128*ASTR + BK*BSTR)   // 4672 floats per stage

template<int N, int K, bool RND>
__device__ __forceinline__ void gemm_body(const float* __restrict__ A,
                                          const float* __restrict__ Bm,
                                          float* __restrict__ C)
{
    __shared__ float sm[2*STG];     // 37376 B static
    const int tid  = threadIdx.x;
    const long bm  = (long)blockIdx.y * 128;
    const long bn  = (long)blockIdx.x * 128;
    const int warp = tid >> 5, lane = tid & 31;
    const int wm   = (warp >> 2) << 6;
    const int wn   = (warp & 3) << 5;
    const int g    = lane >> 2, tg = lane & 3;

    float acc[4][4][4];
    #pragma unroll
    for(int i=0;i<4;i++)
        #pragma unroll
        for(int j=0;j<4;j++)
            #pragma unroll
            for(int k=0;k<4;k++) acc[i][j][k]=0.f;

    const int arow = tid >> 2;
    const int acol = (tid & 3) << 2;
    const int brow = tid >> 5;
    const int bcol = (tid & 31) << 2;

    const int NK = K / BK;

    {
        float* As = sm; float* Bs = sm + 128*ASTR;
        cp16(&As[ arow     *ASTR + acol], &A[(bm+arow   )*(long)K + acol]);
        cp16(&As[(arow+64) *ASTR + acol], &A[(bm+arow+64)*(long)K + acol]);
        cp16(&Bs[ brow     *BSTR + bcol], &Bm[(long)(brow  )*N + bn + bcol]);
        cp16(&Bs[(brow+8)  *BSTR + bcol], &Bm[(long)(brow+8)*N + bn + bcol]);
        cp_commit();
    }

    for(int kb=0; kb<NK; ++kb){
        if(kb+1 < NK){
            const int kn = (kb+1)*BK;
            float* As = sm + ((kb+1)&1)*STG; float* Bs = As + 128*ASTR;
            cp16(&As[ arow     *ASTR + acol], &A[(bm+arow   )*(long)K + kn + acol]);
            cp16(&As[(arow+64) *ASTR + acol], &A[(bm+arow+64)*(long)K + kn + acol]);
            cp16(&Bs[ brow     *BSTR + bcol], &Bm[(long)(kn+brow  )*N + bn + bcol]);
            cp16(&Bs[(brow+8)  *BSTR + bcol], &Bm[(long)(kn+brow+8)*N + bn + bcol]);
            cp_commit();
            cp_wait<1>();
        } else {
            cp_wait<0>();
        }
        __syncthreads();

        // data already tf32-valued: read raw bits, no cvt in the hot loop
        const uint32_t* Au = (const uint32_t*)(sm + (kb&1)*STG);
        const uint32_t* Bu = Au + 128*ASTR;
        #pragma unroll
        for(int ks=0; ks<BK/8; ++ks){
            uint32_t a[4][4], bq[4][2];
            const int c0 = ks*8 + tg;
            #pragma unroll
            for(int mt=0;mt<4;mt++){
                const int r = wm + mt*16 + g;
                a[mt][0]=Au[ r   *ASTR + c0  ];
                a[mt][1]=Au[(r+8)*ASTR + c0  ];
                a[mt][2]=Au[ r   *ASTR + c0+4];
                a[mt][3]=Au[(r+8)*ASTR + c0+4];
            }
            #pragma unroll
            for(int nt=0;nt<4;nt++){
                const int n = wn + nt*8 + g;
                bq[nt][0]=Bu[(ks*8+tg  )*BSTR + n];
                bq[nt][1]=Bu[(ks*8+tg+4)*BSTR + n];
            }
            #pragma unroll
            for(int mt=0;mt<4;mt++)
                #pragma unroll
                for(int nt=0;nt<4;nt++)
                    mma8(acc[mt][nt], a[mt][0],a[mt][1],a[mt][2],a[mt][3],
                         bq[nt][0],bq[nt][1]);
        }
        __syncthreads();
    }

    #pragma unroll
    for(int mt=0;mt<4;mt++){
        const long r = bm + wm + mt*16 + g;
        #pragma unroll
        for(int nt=0;nt<4;nt++){
            const long col = bn + wn + nt*8 + 2*tg;
            if(RND){
                *(float2*)&C[ r   *N + col] = make_float2(rtf(acc[mt][nt][0]), rtf(acc[mt][nt][1]));
                *(float2*)&C[(r+8)*N + col] = make_float2(rtf(acc[mt][nt][2]), rtf(acc[mt][nt][3]));
            }else{
                *(float2*)&C[ r   *N + col] = make_float2(acc[mt][nt][0], acc[mt][nt][1]);
                *(float2*)&C[(r+8)*N + col] = make_float2(acc[mt][nt][2], acc[mt][nt][3]);
            }
        }
    }
}

__global__ void __launch_bounds__(256) k_qkv(const float* __restrict__ x,
                                             const float* __restrict__ w){
    gemm_body<3*C_, C_, true>(x, w, g_qkv);     // round epilogue for attention
}
__global__ void __launch_bounds__(256) k_proj(const float* __restrict__ w,
                                              float* __restrict__ out){
    gemm_body<C_, C_, false>(g_y, w, out);      // final output: full fp32
}

// ---------------------------------------------------------------- attention
// P fragment relayout: MMA C-layout -> A-layout via shuffles (+tf32 round).
__device__ __forceinline__ void frag_c2a(float p0,float p1,float p2,float p3,
    uint32_t&a0,uint32_t&a1,uint32_t&a2,uint32_t&a3, int lane){
    const int tg   = lane & 3;
    const int base = lane & 28;
    const int src  = base | (tg >> 1);
    float v0=__shfl_sync(0xffffffffu,p0,src);
    float v1=__shfl_sync(0xffffffffu,p1,src);
    float v2=__shfl_sync(0xffffffffu,p2,src);
    float v3=__shfl_sync(0xffffffffu,p3,src);
    float w0=__shfl_sync(0xffffffffu,p0,src+2);
    float w1=__shfl_sync(0xffffffffu,p1,src+2);
    float w2=__shfl_sync(0xffffffffu,p2,src+2);
    float w3=__shfl_sync(0xffffffffu,p3,src+2);
    const bool hi = tg & 1;
    a0 = f2tf(hi?v1:v0); a1 = f2tf(hi?v3:v2);
    a2 = f2tf(hi?w1:w0); a3 = f2tf(hi?w3:w2);
}

// One block per (64-row Q tile, batch*head). 4 warps, each owns 16 Q rows.
__global__ void __launch_bounds__(128) k_attn()
{
    __shared__ float Ks[64*68];
    __shared__ float Vs[64*68];

    const int qt  = blockIdx.x;
    const int bh  = blockIdx.y;
    const int b   = bh >> 4, h = bh & 15;
    const int tid = threadIdx.x;
    const int warp= tid >> 5, lane = tid & 31;
    const int g   = lane >> 2, tg = lane & 3;
    const int qr  = warp << 4;

    const long RS = 3*C_;
    const float* base = g_qkv + (long)b*T_*RS;
    const float* Qg = base + (long)(qt*64)*RS + h*HD;
    const float* Kg = base + C_   + h*HD;
    const float* Vg = base + 2*C_ + h*HD;

    // stage Q (x0.125 — exact power of two, stays tf32-valued)
    #pragma unroll
    for(int i=0;i<8;i++){
        int idx = tid + i*128;
        int r = idx >> 4, c = (idx & 15) << 2;
        float4 v = *(const float4*)&Qg[(long)r*RS + c];
        Ks[r*68+c  ] = v.x*0.125f;
        Ks[r*68+c+1] = v.y*0.125f;
        Ks[r*68+c+2] = v.z*0.125f;
        Ks[r*68+c+3] = v.w*0.125f;
    }
    __syncthreads();
    const uint32_t* uKs = (const uint32_t*)Ks;
    const uint32_t* uVs = (const uint32_t*)Vs;
    uint32_t qf[8][4];
    #pragma unroll
    for(int kt=0;kt<8;kt++){
        const int c = kt*8 + tg;
        qf[kt][0]=uKs[(qr+g  )*68 + c  ];
        qf[kt][1]=uKs[(qr+g+8)*68 + c  ];
        qf[kt][2]=uKs[(qr+g  )*68 + c+4];
        qf[kt][3]=uKs[(qr+g+8)*68 + c+4];
    }
    __syncthreads();

    float o[8][4];
    #pragma unroll
    for(int dt=0;dt<8;dt++){ o[dt][0]=0;o[dt][1]=0;o[dt][2]=0;o[dt][3]=0; }
    float m0=-1e30f, m1=-1e30f, l0=0.f, l1=0.f;

    for(int j=0;j<=qt;j++){
        const float* Kj = Kg + (long)(j*64)*RS;
        const float* Vj = Vg + (long)(j*64)*RS;
        #pragma unroll
        for(int i=0;i<8;i++){
            int idx = tid + i*128;
            int r = idx >> 4, c = (idx & 15) << 2;
            cp16(&Ks[r*68+c], &Kj[(long)r*RS + c]);
        }
        cp_commit();
        #pragma unroll
        for(int i=0;i<8;i++){
            int idx = tid + i*128;
            int r = idx >> 4, c = (idx & 15) << 2;
            cp16(&Vs[r*68+c], &Vj[(long)r*RS + c]);
        }
        cp_commit();
        cp_wait<1>();          // K complete; V may still be in flight
        __syncthreads();

        // S = (Q*scale) @ K^T  — K frags read raw (already tf32)
        float s[8][4];
        #pragma unroll
        for(int nt=0;nt<8;nt++){ s[nt][0]=0;s[nt][1]=0;s[nt][2]=0;s[nt][3]=0; }
        #pragma unroll
        for(int kt=0;kt<8;kt++){
            #pragma unroll
            for(int nt=0;nt<8;nt++){
                const int n = nt*8+g, kr = kt*8+tg;
                mma8(s[nt], qf[kt][0],qf[kt][1],qf[kt][2],qf[kt][3],
                     uKs[n*68+kr], uKs[n*68+kr+4]);
            }
        }

        if(j==qt){
            const int r0 = qr+g, r1 = r0+8;
            #pragma unroll
            for(int nt=0;nt<8;nt++){
                const int c0 = nt*8 + 2*tg;
                if(c0   > r0) s[nt][0] = -1e30f;
                if(c0+1 > r0) s[nt][1] = -1e30f;
                if(c0   > r1) s[nt][2] = -1e30f;
                if(c0+1 > r1) s[nt][3] = -1e30f;
            }
        }

        float mx0=-1e30f, mx1=-1e30f;
        #pragma unroll
        for(int nt=0;nt<8;nt++){
            mx0 = fmaxf(mx0, fmaxf(s[nt][0], s[nt][1]));
            mx1 = fmaxf(mx1, fmaxf(s[nt][2], s[nt][3]));
        }
        mx0 = fmaxf(mx0, __shfl_xor_sync(0xffffffffu, mx0, 1));
        mx0 = fmaxf(mx0, __shfl_xor_sync(0xffffffffu, mx0, 2));
        mx1 = fmaxf(mx1, __shfl_xor_sync(0xffffffffu, mx1, 1));
        mx1 = fmaxf(mx1, __shfl_xor_sync(0xffffffffu, mx1, 2));
        const float mn0 = fmaxf(m0, mx0), mn1 = fmaxf(m1, mx1);
        const float al0 = __expf(m0 - mn0), al1 = __expf(m1 - mn1);
        m0 = mn0; m1 = mn1;
        float su0 = 0.f, su1 = 0.f;
        #pragma unroll
        for(int nt=0;nt<8;nt++){
            s[nt][0]=__expf(s[nt][0]-mn0); s[nt][1]=__expf(s[nt][1]-mn0);
            s[nt][2]=__expf(s[nt][2]-mn1); s[nt][3]=__expf(s[nt][3]-mn1);
            su0 += s[nt][0]+s[nt][1];
            su1 += s[nt][2]+s[nt][3];
        }
        su0 += __shfl_xor_sync(0xffffffffu, su0, 1);
        su0 += __shfl_xor_sync(0xffffffffu, su0, 2);
        su1 += __shfl_xor_sync(0xffffffffu, su1, 1);
        su1 += __shfl_xor_sync(0xffffffffu, su1, 2);
        l0 = l0*al0 + su0; l1 = l1*al1 + su1;
        #pragma unroll
        for(int dt=0;dt<8;dt++){
            o[dt][0]*=al0; o[dt][1]*=al0; o[dt][2]*=al1; o[dt][3]*=al1;
        }

        // O += P @ V — V frags read raw (already tf32)
        cp_wait<0>();
        __syncthreads();
        #pragma unroll
        for(int kt=0;kt<8;kt++){
            uint32_t a0,a1,a2,a3;
            frag_c2a(s[kt][0],s[kt][1],s[kt][2],s[kt][3], a0,a1,a2,a3, lane);
            #pragma unroll
            for(int dt=0;dt<8;dt++){
                mma8(o[dt], a0,a1,a2,a3,
                     uVs[(kt*8+tg  )*68 + dt*8+g],
                     uVs[(kt*8+tg+4)*68 + dt*8+g]);
            }
        }
        __syncthreads();
    }

    // epilogue: O / l, rounded to tf32 (feeds the proj GEMM)
    const float i0 = 1.f/l0, i1 = 1.f/l1;
    const long r0 = (long)(b*T_ + qt*64 + qr + g);
    #pragma unroll
    for(int dt=0;dt<8;dt++){
        const long col = h*HD + dt*8 + 2*tg;
        *(float2*)&g_y[ r0   *C_ + col] = make_float2(rtf(o[dt][0]*i0), rtf(o[dt][1]*i0));
        *(float2*)&g_y[(r0+8)*C_ + col] = make_float2(rtf(o[dt][2]*i1), rtf(o[dt][3]*i1));
    }
}

// ---------------------------------------------------------------- launch
extern "C" void kernel_launch(void* const* d_in, const int* in_sizes, int n_in,
                              void* d_out, int out_size)
{
    const float* x     = (const float*)d_in[0];   // (4,2048,1024)
    const float* wqkv  = (const float*)d_in[1];   // (1024,3072)
    const float* wproj = (const float*)d_in[2];   // (1024,1024)
    float* out = (float*)d_out;                   // (4,2048,1024)

    float* gx  = nullptr; cudaGetSymbolAddress((void**)&gx,  g_x);
    float* gwq = nullptr; cudaGetSymbolAddress((void**)&gwq, g_wqkv);
    float* gwp = nullptr; cudaGetSymbolAddress((void**)&gwp, g_wprj);

    k_round<<<2048, 256>>>(x,     gx,  M_*C_);
    k_round<<<1024, 256>>>(wqkv,  gwq, C_*3*C_);
    k_round<<<512,  256>>>(wproj, gwp, C_*C_);

    k_qkv <<<dim3(3*C_/128, M_/128), 256>>>(gx, gwq);
    k_attn<<<dim3(T_/64, B_*NH),     128>>>();
    k_proj<<<dim3(C_/128,  M_/128),  256>>>(gwp, out);
}